// round 1
// baseline (speedup 1.0000x reference)
#include <cuda_runtime.h>
#include <cuda_bf16.h>
#include <math.h>

typedef unsigned long long ull;

#define DIMV   8192
#define NKV    8
#define NREP   8
#define HD     128
#define KVLEN  4096
#define FDV    2048
#define FEV    1024
#define EV     8
#define BV     8
#define NSPLIT 32

// ---------------- scratch (device globals; no allocation allowed) ----------------
__device__ float g_an[BV * DIMV];
__device__ float g_qkv[BV * 10240];
__device__ float g_q[BV * 64 * HD];
__device__ float g_nk[BV * NKV * HD];
__device__ float g_nv[BV * NKV * HD];
__device__ float g_pm[BV * NKV * NSPLIT * NREP];
__device__ float g_pl[BV * NKV * NSPLIT * NREP];
__device__ float g_pacc[BV * NKV * NSPLIT * NREP * HD];
__device__ float g_attnout[BV * DIMV];
__device__ float g_h[BV * DIMV];
__device__ float g_fin[BV * DIMV];
__device__ float g_ffh1[BV * FDV];
__device__ float g_ffh3[BV * FDV];
__device__ float g_ffact[BV * FDV];
__device__ float g_expw[BV * EV];
__device__ int   g_used[EV];
__device__ float g_eh1[EV * BV * FEV];
__device__ float g_eh3[EV * BV * FEV];
__device__ float g_eact[EV * BV * FEV];

// ---------------- f32x2 helpers ----------------
__device__ __forceinline__ ull pk2(float lo, float hi) {
    ull r; asm("mov.b64 %0, {%1, %2};" : "=l"(r) : "f"(lo), "f"(hi)); return r;
}
__device__ __forceinline__ void upk2(ull v, float& lo, float& hi) {
    asm("mov.b64 {%0, %1}, %2;" : "=f"(lo), "=f"(hi) : "l"(v));
}
__device__ __forceinline__ void fma2(ull& acc, ull a, ull b) {
    asm("fma.rn.f32x2 %0, %1, %2, %0;" : "+l"(acc) : "l"(a), "l"(b));
}

__device__ __forceinline__ float gelu_exact(float x) {
    return 0.5f * x * (1.0f + erff(x * 0.70710678118654752f));
}

// ---------------- init / zero ----------------
__global__ void k_init(const float* __restrict__ x) {
    int i = blockIdx.x * blockDim.x + threadIdx.x;
    int st = gridDim.x * blockDim.x;
    for (int j = i; j < BV * 10240; j += st) g_qkv[j] = 0.f;
    for (int j = i; j < BV * DIMV; j += st) g_h[j] = x[j];
    for (int j = i; j < BV * FDV; j += st) { g_ffh1[j] = 0.f; g_ffh3[j] = 0.f; }
    for (int j = i; j < EV * BV * FEV; j += st) { g_eh1[j] = 0.f; g_eh3[j] = 0.f; }
    if (i < EV) g_used[i] = 0;
}

// ---------------- rmsnorm ----------------
__device__ __forceinline__ void rms_core(const float* __restrict__ in,
                                         const float* __restrict__ w,
                                         float* __restrict__ outp,
                                         float* __restrict__ cpy) {
    int b = blockIdx.x;
    int t = threadIdx.x;                       // 512 threads
    const float* xr = in + b * DIMV;
    float v[16];
    float ss = 0.f;
#pragma unroll
    for (int i = 0; i < 16; i++) { v[i] = xr[t + i * 512]; ss = fmaf(v[i], v[i], ss); }
#pragma unroll
    for (int o = 16; o; o >>= 1) ss += __shfl_xor_sync(0xffffffffu, ss, o);
    __shared__ float red[16];
    __shared__ float sinv;
    if ((t & 31) == 0) red[t >> 5] = ss;
    __syncthreads();
    if (t == 0) {
        float s = 0.f;
        for (int i = 0; i < 16; i++) s += red[i];
        sinv = rsqrtf(s * (1.0f / 8192.0f) + 1e-5f);
    }
    __syncthreads();
    float inv = sinv;
#pragma unroll
    for (int i = 0; i < 16; i++) {
        int idx = t + i * 512;
        outp[b * DIMV + idx] = v[i] * inv * w[idx];
        if (cpy) cpy[b * DIMV + idx] = v[i];
    }
}

__global__ __launch_bounds__(512) void k_rms1(const float* __restrict__ x,
                                              const float* __restrict__ w) {
    rms_core(x, w, g_an, nullptr);
}
__global__ __launch_bounds__(512) void k_rms2(const float* __restrict__ w,
                                              float* __restrict__ dout) {
    rms_core(g_h, w, g_fin, dout);
}

// ---------------- KN GEMV: qkv = an @ wqkv   (W[K=8192][N=10240]) ----------------
// grid (20 j-tiles of 512, 16 k-splits of 512), 128 threads, each thread owns 4 j.
__global__ __launch_bounds__(128) void k_qkv(const float* __restrict__ W) {
    __shared__ float2 sx[8][512];              // duplicated (x,x) pairs
    int t = threadIdx.x;
    int ks = blockIdx.y * 512;
    for (int i = t; i < 8 * 512; i += 128) {
        int b = i >> 9, k = i & 511;
        float v = g_an[b * DIMV + ks + k];
        sx[b][k] = make_float2(v, v);
    }
    __syncthreads();
    int j0 = blockIdx.x * 512 + t * 4;
    ull acc[8][2];
#pragma unroll
    for (int b = 0; b < 8; b++) { acc[b][0] = 0ULL; acc[b][1] = 0ULL; }
    const float* Wp = W + (size_t)ks * 10240 + j0;
#pragma unroll 4
    for (int d = 0; d < 512; d++) {
        float4 w4 = *(const float4*)(Wp + (size_t)d * 10240);
        ull wl = pk2(w4.x, w4.y);
        ull wh = pk2(w4.z, w4.w);
#pragma unroll
        for (int b = 0; b < 8; b++) {
            ull x2 = *(const ull*)&sx[b][d];
            fma2(acc[b][0], x2, wl);
            fma2(acc[b][1], x2, wh);
        }
    }
#pragma unroll
    for (int b = 0; b < 8; b++) {
        float lo, hi;
        upk2(acc[b][0], lo, hi);
        atomicAdd(g_qkv + b * 10240 + j0 + 0, lo);
        atomicAdd(g_qkv + b * 10240 + j0 + 1, hi);
        upk2(acc[b][1], lo, hi);
        atomicAdd(g_qkv + b * 10240 + j0 + 2, lo);
        atomicAdd(g_qkv + b * 10240 + j0 + 3, hi);
    }
}

// ---------------- RoPE + split qkv ----------------
__global__ __launch_bounds__(128) void k_rope(const float* __restrict__ cosn,
                                              const float* __restrict__ sinn) {
    int bk = blockIdx.x;                       // 64 blocks: b*8 + kvh
    int b = bk >> 3, kvh = bk & 7;
    int t = threadIdx.x;                       // 128
    const float* src = g_qkv + b * 10240 + kvh * 1280;
    for (int pidx = t; pidx < 512; pidx += 128) {
        int r = pidx >> 6, i = pidx & 63;
        float re = src[r * 128 + 2 * i];
        float im = src[r * 128 + 2 * i + 1];
        float c = cosn[i], s = sinn[i];
        float* dst = g_q + (size_t)(b * 64 + kvh * 8 + r) * HD;
        dst[2 * i]     = re * c - im * s;
        dst[2 * i + 1] = re * s + im * c;
    }
    if (t < 64) {
        int i = t;
        float c = cosn[i], s = sinn[i];
        float re = src[1024 + 2 * i], im = src[1024 + 2 * i + 1];
        float* dk = g_nk + (b * 8 + kvh) * HD;
        dk[2 * i]     = re * c - im * s;
        dk[2 * i + 1] = re * s + im * c;
        float* dv = g_nv + (b * 8 + kvh) * HD;
        dv[2 * i]     = src[1152 + 2 * i];
        dv[2 * i + 1] = src[1152 + 2 * i + 1];
    }
}

// ---------------- attention: flash-decoding partials ----------------
// grid (32 splits, 8 kvh, 8 b); 8 warps = 8 q-heads per kv head.
__global__ __launch_bounds__(256) void k_attn(const float* __restrict__ ck,
                                              const float* __restrict__ cv,
                                              const int* __restrict__ spp) {
    int split = blockIdx.x, kvh = blockIdx.y, b = blockIdx.z;
    int warp = threadIdx.x >> 5, lane = threadIdx.x & 31;
    int sp = *spp;
    int h = kvh * 8 + warp;
    float4 q = *(const float4*)(g_q + (size_t)(b * 64 + h) * HD + lane * 4);
    float m = -1e30f, l = 0.f;
    float4 acc = make_float4(0.f, 0.f, 0.f, 0.f);
    int p0 = split * (KVLEN / NSPLIT);
    const float scale = 0.08838834764831845f;  // 1/sqrt(128)
    for (int pp = 0; pp < KVLEN / NSPLIT; pp++) {
        int pos = p0 + pp;
        size_t coff = (((size_t)b * KVLEN + pos) * NKV + kvh) * HD;
        const float* kr = (pos == sp) ? (g_nk + (b * 8 + kvh) * HD) : (ck + coff);
        float4 k4 = *(const float4*)(kr + lane * 4);
        float d = q.x * k4.x + q.y * k4.y + q.z * k4.z + q.w * k4.w;
#pragma unroll
        for (int o = 16; o; o >>= 1) d += __shfl_xor_sync(0xffffffffu, d, o);
        float s = d * scale;
        float mn = fmaxf(m, s);
        float c = __expf(m - mn);
        float p = __expf(s - mn);
        m = mn;
        l = l * c + p;
        const float* vr = (pos == sp) ? (g_nv + (b * 8 + kvh) * HD) : (cv + coff);
        float4 v4 = *(const float4*)(vr + lane * 4);
        acc.x = acc.x * c + p * v4.x;
        acc.y = acc.y * c + p * v4.y;
        acc.z = acc.z * c + p * v4.z;
        acc.w = acc.w * c + p * v4.w;
    }
    int idx = ((b * 8 + kvh) * NSPLIT + split) * NREP + warp;
    if (lane == 0) { g_pm[idx] = m; g_pl[idx] = l; }
    *(float4*)(g_pacc + (size_t)idx * HD + lane * 4) = acc;
}

// ---------------- attention: combine partials ----------------
__global__ __launch_bounds__(256) void k_comb() {
    int bk = blockIdx.x;                       // 64: b*8+kvh
    int b = bk >> 3, kvh = bk & 7;
    int warp = threadIdx.x >> 5, lane = threadIdx.x & 31;  // warp = r
    int base = ((b * 8 + kvh) * NSPLIT) * NREP + warp;
    float mg = -1e30f;
    for (int s = 0; s < NSPLIT; s++) mg = fmaxf(mg, g_pm[base + s * NREP]);
    float lg = 0.f;
    float4 a = make_float4(0.f, 0.f, 0.f, 0.f);
    for (int s = 0; s < NSPLIT; s++) {
        int idx = base + s * NREP;
        float c = __expf(g_pm[idx] - mg);
        lg += g_pl[idx] * c;
        float4 pa = *(const float4*)(g_pacc + (size_t)idx * HD + lane * 4);
        a.x += c * pa.x; a.y += c * pa.y; a.z += c * pa.z; a.w += c * pa.w;
    }
    float inv = 1.0f / lg;
    float* dst = g_attnout + (size_t)b * DIMV + (kvh * 8 + warp) * HD + lane * 4;
    *(float4*)dst = make_float4(a.x * inv, a.y * inv, a.z * inv, a.w * inv);
}

// ---------------- NK GEMV core: Y[b][n] += sum_k X[b][k]*W[n][k] ----------------
// 256 threads = 8 warps, each warp owns 4 consecutive n. grid.x = N/32 tiles,
// grid.y = K/kc_len splits. f32x2 packed over k-pairs.
__device__ __forceinline__ void gemv_nk_core(const float* __restrict__ X,
                                             const float* __restrict__ W,
                                             float* __restrict__ Y,
                                             int N, int K, int kc_len) {
    __shared__ float sx[8][1024];
    const int lane = threadIdx.x & 31;
    const int warp = threadIdx.x >> 5;
    const int n0 = blockIdx.x * 32 + warp * 4;
    const int k0 = blockIdx.y * kc_len;

    const float* Wr0 = W + (size_t)(n0 + 0) * K;
    const float* Wr1 = W + (size_t)(n0 + 1) * K;
    const float* Wr2 = W + (size_t)(n0 + 2) * K;
    const float* Wr3 = W + (size_t)(n0 + 3) * K;

    ull acc[4][8];
#pragma unroll
    for (int r = 0; r < 4; r++)
#pragma unroll
        for (int b = 0; b < 8; b++) acc[r][b] = 0ULL;

    for (int ks = k0; ks < k0 + kc_len; ks += 1024) {
        __syncthreads();
#pragma unroll
        for (int i = threadIdx.x; i < 2048; i += 256) {
            int b = i >> 8, kq = i & 255;
            *(float4*)&sx[b][kq * 4] = *(const float4*)(X + (size_t)b * K + ks + kq * 4);
        }
        __syncthreads();
#pragma unroll 2
        for (int kk = lane * 4; kk < 1024; kk += 128) {
            float4 w0 = *(const float4*)(Wr0 + ks + kk);
            float4 w1 = *(const float4*)(Wr1 + ks + kk);
            float4 w2 = *(const float4*)(Wr2 + ks + kk);
            float4 w3 = *(const float4*)(Wr3 + ks + kk);
            ull xl[8], xh[8];
#pragma unroll
            for (int b = 0; b < 8; b++) {
                xl[b] = *(const ull*)&sx[b][kk];
                xh[b] = *(const ull*)&sx[b][kk + 2];
            }
            ull wl, wh;
            wl = pk2(w0.x, w0.y); wh = pk2(w0.z, w0.w);
#pragma unroll
            for (int b = 0; b < 8; b++) { fma2(acc[0][b], wl, xl[b]); fma2(acc[0][b], wh, xh[b]); }
            wl = pk2(w1.x, w1.y); wh = pk2(w1.z, w1.w);
#pragma unroll
            for (int b = 0; b < 8; b++) { fma2(acc[1][b], wl, xl[b]); fma2(acc[1][b], wh, xh[b]); }
            wl = pk2(w2.x, w2.y); wh = pk2(w2.z, w2.w);
#pragma unroll
            for (int b = 0; b < 8; b++) { fma2(acc[2][b], wl, xl[b]); fma2(acc[2][b], wh, xh[b]); }
            wl = pk2(w3.x, w3.y); wh = pk2(w3.z, w3.w);
#pragma unroll
            for (int b = 0; b < 8; b++) { fma2(acc[3][b], wl, xl[b]); fma2(acc[3][b], wh, xh[b]); }
        }
    }
#pragma unroll
    for (int r = 0; r < 4; r++) {
#pragma unroll
        for (int b = 0; b < 8; b++) {
            float lo, hi;
            upk2(acc[r][b], lo, hi);
            float v = lo + hi;
#pragma unroll
            for (int o = 16; o; o >>= 1) v += __shfl_down_sync(0xffffffffu, v, o);
            if (lane == 0) atomicAdd(Y + (size_t)b * N + n0 + r, v);
        }
    }
}

__global__ __launch_bounds__(256) void k_wo(const float* __restrict__ W) {
    gemv_nk_core(g_attnout, W, g_h, DIMV, DIMV, 2048);
}
__global__ __launch_bounds__(256) void k_ffn13(const float* __restrict__ W1,
                                               const float* __restrict__ W3) {
    const float* W = (blockIdx.z & 1) ? W3 : W1;
    float* Y = (blockIdx.z & 1) ? g_ffh3 : g_ffh1;
    gemv_nk_core(g_fin, W, Y, FDV, DIMV, 2048);
}
__global__ __launch_bounds__(256) void k_moe13(const float* __restrict__ W1,
                                               const float* __restrict__ W3) {
    int e = blockIdx.z >> 1;
    if (!g_used[e]) return;
    const float* W = ((blockIdx.z & 1) ? W3 : W1) + (size_t)e * FEV * DIMV;
    float* Y = ((blockIdx.z & 1) ? g_eh3 : g_eh1) + e * BV * FEV;
    gemv_nk_core(g_fin, W, Y, FEV, DIMV, 4096);
}
__global__ __launch_bounds__(256) void k_ffn2(const float* __restrict__ W,
                                              float* __restrict__ out) {
    gemv_nk_core(g_ffact, W, out, DIMV, FDV, 1024);
}
__global__ __launch_bounds__(256) void k_moe2(const float* __restrict__ W,
                                              float* __restrict__ out) {
    int e = blockIdx.z;
    if (!g_used[e]) return;
    gemv_nk_core(g_eact + e * BV * FEV, W + (size_t)e * DIMV * FEV, out, DIMV, FEV, 1024);
}

// ---------------- gating: softmax + top-2 ----------------
__global__ __launch_bounds__(256) void k_gate(const float* __restrict__ gw) {
    int b = blockIdx.x;
    int warp = threadIdx.x >> 5, lane = threadIdx.x & 31;  // warp = expert
    __shared__ float lg[EV];
    const float* x = g_fin + b * DIMV;
    const float* w = gw + warp * DIMV;
    float s = 0.f;
    for (int k = lane * 4; k < DIMV; k += 128) {
        float4 xv = *(const float4*)(x + k);
        float4 wv = *(const float4*)(w + k);
        s += xv.x * wv.x + xv.y * wv.y + xv.z * wv.z + xv.w * wv.w;
    }
#pragma unroll
    for (int o = 16; o; o >>= 1) s += __shfl_xor_sync(0xffffffffu, s, o);
    if (lane == 0) lg[warp] = s;
    __syncthreads();
    if (threadIdx.x == 0) {
        float mx = -1e30f;
        for (int e = 0; e < EV; e++) mx = fmaxf(mx, lg[e]);
        float p[EV], sum = 0.f;
        for (int e = 0; e < EV; e++) { p[e] = __expf(lg[e] - mx); sum += p[e]; }
        for (int e = 0; e < EV; e++) p[e] /= sum;
        int i1 = 0;
        for (int e = 1; e < EV; e++) if (p[e] > p[i1]) i1 = e;
        int i2 = -1;
        for (int e = 0; e < EV; e++) if (e != i1 && (i2 < 0 || p[e] > p[i2])) i2 = e;
        for (int e = 0; e < EV; e++) g_expw[b * EV + e] = 0.f;
        g_expw[b * EV + i1] = p[i1];
        g_expw[b * EV + i2] = p[i2];
        atomicOr(&g_used[i1], 1);
        atomicOr(&g_used[i2], 1);
    }
}

// ---------------- activations ----------------
__global__ void k_actd() {
    int i = blockIdx.x * 256 + threadIdx.x;
    if (i < BV * FDV) g_ffact[i] = gelu_exact(g_ffh1[i]) * g_ffh3[i];
}
__global__ void k_actm() {
    int i = blockIdx.x * 256 + threadIdx.x;
    if (i < EV * BV * FEV) {
        int e = i >> 13;
        int b = (i >> 10) & 7;
        g_eact[i] = gelu_exact(g_eh1[i]) * g_eh3[i] * g_expw[b * EV + e];
    }
}

// ---------------- launch ----------------
extern "C" void kernel_launch(void* const* d_in, const int* in_sizes, int n_in,
                              void* d_out, int out_size) {
    const float* x    = (const float*)d_in[0];
    const float* fc   = (const float*)d_in[2];
    const float* fs   = (const float*)d_in[3];
    const float* ck   = (const float*)d_in[4];
    const float* cv   = (const float*)d_in[5];
    const float* wqkv = (const float*)d_in[6];
    const float* wo   = (const float*)d_in[7];
    const float* anw  = (const float*)d_in[8];
    const float* fnw  = (const float*)d_in[9];
    const float* w1   = (const float*)d_in[10];
    const float* w2   = (const float*)d_in[11];
    const float* w3   = (const float*)d_in[12];
    const float* gw   = (const float*)d_in[13];
    const float* m1   = (const float*)d_in[14];
    const float* m2   = (const float*)d_in[15];
    const float* m3   = (const float*)d_in[16];
    const int*   sp   = (const int*)d_in[17];
    float* out = (float*)d_out;

    k_init<<<128, 256>>>(x);
    k_rms1<<<8, 512>>>(x, anw);
    k_qkv<<<dim3(20, 16), 128>>>(wqkv);
    k_rope<<<64, 128>>>(fc, fs);
    k_attn<<<dim3(NSPLIT, NKV, BV), 256>>>(ck, cv, sp);
    k_comb<<<64, 256>>>();
    k_wo<<<dim3(DIMV / 32, 4), 256>>>(wo);
    k_rms2<<<8, 512>>>(fnw, out);          // writes g_fin; copies h into d_out
    k_gate<<<8, 256>>>(gw);
    k_ffn13<<<dim3(FDV / 32, 4, 2), 256>>>(w1, w3);
    k_moe13<<<dim3(FEV / 32, 2, 16), 256>>>(m1, m3);
    k_actd<<<(BV * FDV + 255) / 256, 256>>>();
    k_actm<<<(EV * BV * FEV + 255) / 256, 256>>>();
    k_ffn2<<<dim3(DIMV / 32, 2), 256>>>(w2, out);
    k_moe2<<<dim3(DIMV / 32, 1, EV), 256>>>(m2, out);
}

// round 4
// speedup vs baseline: 1.3802x; 1.3802x over previous
#include <cuda_runtime.h>
#include <math.h>

typedef unsigned long long ull;

#define DIMV   8192
#define NKV    8
#define NREP   8
#define HD     128
#define KVLEN  4096
#define FDV    2048
#define FEV    1024
#define EV     8
#define BV     8
#define NSPLIT 32

// ---------------- scratch ----------------
__device__ float g_an[BV * DIMV];
__device__ float g_qkv[BV * 10240];
__device__ float g_q[BV * 64 * HD];
__device__ float g_nk[BV * NKV * HD];
__device__ float g_nv[BV * NKV * HD];
__device__ float g_pm[BV * NKV * NSPLIT * NREP];
__device__ float g_pl[BV * NKV * NSPLIT * NREP];
__device__ float g_pacc[BV * NKV * NSPLIT * NREP * HD];
__device__ float g_attnout[BV * DIMV];
__device__ float g_h[BV * DIMV];
__device__ float g_fin[BV * DIMV];
__device__ float g_ffh1[BV * FDV];
__device__ float g_ffh3[BV * FDV];
__device__ float g_ffact[BV * FDV];
__device__ float g_expw[BV * EV];
__device__ int   g_used[EV];
__device__ float g_eh1[EV * BV * FEV];
__device__ float g_eh3[EV * BV * FEV];
__device__ float g_eact[EV * BV * FEV];

// ---------------- f32x2 helpers ----------------
__device__ __forceinline__ ull pk2(float lo, float hi) {
    ull r; asm("mov.b64 %0, {%1, %2};" : "=l"(r) : "f"(lo), "f"(hi)); return r;
}
__device__ __forceinline__ void upk2(ull v, float& lo, float& hi) {
    asm("mov.b64 {%0, %1}, %2;" : "=f"(lo), "=f"(hi) : "l"(v));
}
__device__ __forceinline__ void fma2(ull& acc, ull a, ull b) {
    asm("fma.rn.f32x2 %0, %1, %2, %0;" : "+l"(acc) : "l"(a), "l"(b));
}
__device__ __forceinline__ float gelu_exact(float x) {
    return 0.5f * x * (1.0f + erff(x * 0.70710678118654752f));
}

// ---------------- init ----------------
__global__ void k_init(const float* __restrict__ x) {
    int i = blockIdx.x * blockDim.x + threadIdx.x;
    int st = gridDim.x * blockDim.x;
    for (int j = i; j < BV * 10240; j += st) g_qkv[j] = 0.f;
    for (int j = i; j < BV * DIMV; j += st) g_h[j] = x[j];
    for (int j = i; j < BV * FDV; j += st) { g_ffh1[j] = 0.f; g_ffh3[j] = 0.f; }
    for (int j = i; j < EV * BV * FEV; j += st) { g_eh1[j] = 0.f; g_eh3[j] = 0.f; }
    if (i < EV) g_used[i] = 0;
}

// ---------------- rmsnorm ----------------
__device__ __forceinline__ void rms_core(const float* __restrict__ in,
                                         const float* __restrict__ w,
                                         float* __restrict__ outp,
                                         float* __restrict__ cpy) {
    int b = blockIdx.x;
    int t = threadIdx.x;
    const float* xr = in + b * DIMV;
    float v[16];
    float ss = 0.f;
#pragma unroll
    for (int i = 0; i < 16; i++) { v[i] = xr[t + i * 512]; ss = fmaf(v[i], v[i], ss); }
#pragma unroll
    for (int o = 16; o; o >>= 1) ss += __shfl_xor_sync(0xffffffffu, ss, o);
    __shared__ float red[16];
    __shared__ float sinv;
    if ((t & 31) == 0) red[t >> 5] = ss;
    __syncthreads();
    if (t == 0) {
        float s = 0.f;
        for (int i = 0; i < 16; i++) s += red[i];
        sinv = rsqrtf(s * (1.0f / 8192.0f) + 1e-5f);
    }
    __syncthreads();
    float inv = sinv;
#pragma unroll
    for (int i = 0; i < 16; i++) {
        int idx = t + i * 512;
        outp[b * DIMV + idx] = v[i] * inv * w[idx];
        if (cpy) cpy[b * DIMV + idx] = v[i];
    }
}
__global__ __launch_bounds__(512) void k_rms1(const float* __restrict__ x,
                                              const float* __restrict__ w) {
    rms_core(x, w, g_an, nullptr);
}
__global__ __launch_bounds__(512) void k_rms2(const float* __restrict__ w,
                                              float* __restrict__ dout) {
    rms_core(g_h, w, g_fin, dout);
}

// ---------------- KN GEMV: qkv = an @ wqkv ----------------
// grid (10 j-tiles of 1024, 32 k-splits of 256), 256 threads, 4 j per thread.
__global__ __launch_bounds__(256) void k_qkv(const float* __restrict__ W) {
    __shared__ float2 sx[8][256];
    int t = threadIdx.x;
    int ks = blockIdx.y * 256;
    for (int i = t; i < 8 * 256; i += 256) {
        int b = i >> 8, k = i & 255;
        float v = g_an[b * DIMV + ks + k];
        sx[b][k] = make_float2(v, v);
    }
    __syncthreads();
    int j0 = blockIdx.x * 1024 + t * 4;
    ull acc[8][2];
#pragma unroll
    for (int b = 0; b < 8; b++) { acc[b][0] = 0ULL; acc[b][1] = 0ULL; }
    const float* Wp = W + (size_t)ks * 10240 + j0;
#pragma unroll 8
    for (int d = 0; d < 256; d++) {
        float4 w4 = *(const float4*)(Wp + (size_t)d * 10240);
        ull wl = pk2(w4.x, w4.y);
        ull wh = pk2(w4.z, w4.w);
#pragma unroll
        for (int b = 0; b < 8; b++) {
            ull x2 = *(const ull*)&sx[b][d];
            fma2(acc[b][0], x2, wl);
            fma2(acc[b][1], x2, wh);
        }
    }
#pragma unroll
    for (int b = 0; b < 8; b++) {
        float lo, hi;
        upk2(acc[b][0], lo, hi);
        atomicAdd(g_qkv + b * 10240 + j0 + 0, lo);
        atomicAdd(g_qkv + b * 10240 + j0 + 1, hi);
        upk2(acc[b][1], lo, hi);
        atomicAdd(g_qkv + b * 10240 + j0 + 2, lo);
        atomicAdd(g_qkv + b * 10240 + j0 + 3, hi);
    }
}

// ---------------- flat RoPE ----------------
__global__ __launch_bounds__(256) void k_rope(const float* __restrict__ cosn,
                                              const float* __restrict__ sinn) {
    int i = blockIdx.x * 256 + threadIdx.x;
    if (i < 32768) {                              // q pairs
        int pair = i & 63, r = (i >> 6) & 7, kvh = (i >> 9) & 7, b = i >> 12;
        const float* src = g_qkv + b * 10240 + kvh * 1280 + r * 128;
        float re = src[2 * pair], im = src[2 * pair + 1];
        float c = cosn[pair], s = sinn[pair];
        float* dst = g_q + (size_t)(b * 64 + kvh * 8 + r) * HD;
        dst[2 * pair]     = re * c - im * s;
        dst[2 * pair + 1] = re * s + im * c;
    } else if (i < 36864) {                       // k pairs
        int j = i - 32768;
        int pair = j & 63, kvh = (j >> 6) & 7, b = j >> 9;
        const float* src = g_qkv + b * 10240 + kvh * 1280 + 1024;
        float re = src[2 * pair], im = src[2 * pair + 1];
        float c = cosn[pair], s = sinn[pair];
        float* dk = g_nk + (b * 8 + kvh) * HD;
        dk[2 * pair]     = re * c - im * s;
        dk[2 * pair + 1] = re * s + im * c;
    } else if (i < 40960) {                       // v copy
        int j = i - 36864;
        int pair = j & 63, kvh = (j >> 6) & 7, b = j >> 9;
        const float* src = g_qkv + b * 10240 + kvh * 1280 + 1152;
        float* dv = g_nv + (b * 8 + kvh) * HD;
        dv[2 * pair]     = src[2 * pair];
        dv[2 * pair + 1] = src[2 * pair + 1];
    }
}

// ---------------- attention partials (flash decoding, unroll 4) ----------------
__global__ __launch_bounds__(256) void k_attn(const float* __restrict__ ck,
                                              const float* __restrict__ cv,
                                              const float* __restrict__ mask,
                                              const int* __restrict__ spp) {
    int split = blockIdx.x, kvh = blockIdx.y, b = blockIdx.z;
    int warp = threadIdx.x >> 5, lane = threadIdx.x & 31;
    int sp = *spp;
    int h = kvh * 8 + warp;
    float4 q = *(const float4*)(g_q + (size_t)(b * 64 + h) * HD + lane * 4);
    const float* nkp = g_nk + (b * 8 + kvh) * HD + lane * 4;
    const float* nvp = g_nv + (b * 8 + kvh) * HD + lane * 4;
    float m = -1e30f, l = 0.f;
    float4 acc = make_float4(0.f, 0.f, 0.f, 0.f);
    int p0 = split * (KVLEN / NSPLIT);
    const float scale = 0.08838834764831845f;
    for (int pp = 0; pp < KVLEN / NSPLIT; pp += 4) {
        float d[4];
        float4 v4[4];
        float mk[4];
#pragma unroll
        for (int u = 0; u < 4; u++) {
            int pos = p0 + pp + u;
            size_t coff = (((size_t)b * KVLEN + pos) * NKV + kvh) * HD + lane * 4;
            const float* kr = (pos == sp) ? nkp : (ck + coff);
            float4 k4 = *(const float4*)kr;
            const float* vr = (pos == sp) ? nvp : (cv + coff);
            v4[u] = *(const float4*)vr;
            mk[u] = mask[pos];
            d[u] = q.x * k4.x + q.y * k4.y + q.z * k4.z + q.w * k4.w;
        }
#pragma unroll
        for (int o = 16; o; o >>= 1) {
#pragma unroll
            for (int u = 0; u < 4; u++) d[u] += __shfl_xor_sync(0xffffffffu, d[u], o);
        }
        float s0 = d[0] * scale + mk[0];
        float s1 = d[1] * scale + mk[1];
        float s2 = d[2] * scale + mk[2];
        float s3 = d[3] * scale + mk[3];
        float mn = fmaxf(fmaxf(fmaxf(s0, s1), fmaxf(s2, s3)), m);
        float c  = __expf(m - mn);
        float e0 = __expf(s0 - mn), e1 = __expf(s1 - mn);
        float e2 = __expf(s2 - mn), e3 = __expf(s3 - mn);
        m = mn;
        l = l * c + (e0 + e1) + (e2 + e3);
        acc.x = fmaf(acc.x, c, e0 * v4[0].x + e1 * v4[1].x + e2 * v4[2].x + e3 * v4[3].x);
        acc.y = fmaf(acc.y, c, e0 * v4[0].y + e1 * v4[1].y + e2 * v4[2].y + e3 * v4[3].y);
        acc.z = fmaf(acc.z, c, e0 * v4[0].z + e1 * v4[1].z + e2 * v4[2].z + e3 * v4[3].z);
        acc.w = fmaf(acc.w, c, e0 * v4[0].w + e1 * v4[1].w + e2 * v4[2].w + e3 * v4[3].w);
    }
    int idx = ((b * 8 + kvh) * NSPLIT + split) * NREP + warp;
    if (lane == 0) { g_pm[idx] = m; g_pl[idx] = l; }
    *(float4*)(g_pacc + (size_t)idx * HD + lane * 4) = acc;
}

// ---------------- combine ----------------
__global__ __launch_bounds__(256) void k_comb() {
    int bk = blockIdx.x;
    int b = bk >> 3, kvh = bk & 7;
    int warp = threadIdx.x >> 5, lane = threadIdx.x & 31;
    int base = ((b * 8 + kvh) * NSPLIT) * NREP + warp;
    float mg = -1e30f;
    for (int s = 0; s < NSPLIT; s++) mg = fmaxf(mg, g_pm[base + s * NREP]);
    float lg = 0.f;
    float4 a = make_float4(0.f, 0.f, 0.f, 0.f);
    for (int s = 0; s < NSPLIT; s++) {
        int idx = base + s * NREP;
        float c = __expf(g_pm[idx] - mg);
        lg += g_pl[idx] * c;
        float4 pa = *(const float4*)(g_pacc + (size_t)idx * HD + lane * 4);
        a.x += c * pa.x; a.y += c * pa.y; a.z += c * pa.z; a.w += c * pa.w;
    }
    float inv = 1.0f / lg;
    float* dst = g_attnout + (size_t)b * DIMV + (kvh * 8 + warp) * HD + lane * 4;
    *(float4*)dst = make_float4(a.x * inv, a.y * inv, a.z * inv, a.w * inv);
}

// ---------------- NK GEMV core ----------------
__device__ __forceinline__ void gemv_nk(const float* __restrict__ X,
                                        const float* __restrict__ W,
                                        float* __restrict__ Y,
                                        int N, int K, int n_tile, int k0, int kc_len) {
    __shared__ float sx[8][1024];
    const int lane = threadIdx.x & 31;
    const int warp = threadIdx.x >> 5;
    const int n0 = n_tile * 32 + warp * 4;

    const float* Wr0 = W + (size_t)(n0 + 0) * K;
    const float* Wr1 = W + (size_t)(n0 + 1) * K;
    const float* Wr2 = W + (size_t)(n0 + 2) * K;
    const float* Wr3 = W + (size_t)(n0 + 3) * K;

    ull acc[4][8];
#pragma unroll
    for (int r = 0; r < 4; r++)
#pragma unroll
        for (int b = 0; b < 8; b++) acc[r][b] = 0ULL;

    for (int ks = k0; ks < k0 + kc_len; ks += 1024) {
        __syncthreads();
#pragma unroll
        for (int i = threadIdx.x; i < 2048; i += 256) {
            int b = i >> 8, kq = i & 255;
            *(float4*)&sx[b][kq * 4] = *(const float4*)(X + (size_t)b * K + ks + kq * 4);
        }
        __syncthreads();
#pragma unroll 2
        for (int kk = lane * 4; kk < 1024; kk += 128) {
            float4 w0 = *(const float4*)(Wr0 + ks + kk);
            float4 w1 = *(const float4*)(Wr1 + ks + kk);
            float4 w2 = *(const float4*)(Wr2 + ks + kk);
            float4 w3 = *(const float4*)(Wr3 + ks + kk);
            ull xl[8], xh[8];
#pragma unroll
            for (int b = 0; b < 8; b++) {
                xl[b] = *(const ull*)&sx[b][kk];
                xh[b] = *(const ull*)&sx[b][kk + 2];
            }
            ull wl, wh;
            wl = pk2(w0.x, w0.y); wh = pk2(w0.z, w0.w);
#pragma unroll
            for (int b = 0; b < 8; b++) { fma2(acc[0][b], wl, xl[b]); fma2(acc[0][b], wh, xh[b]); }
            wl = pk2(w1.x, w1.y); wh = pk2(w1.z, w1.w);
#pragma unroll
            for (int b = 0; b < 8; b++) { fma2(acc[1][b], wl, xl[b]); fma2(acc[1][b], wh, xh[b]); }
            wl = pk2(w2.x, w2.y); wh = pk2(w2.z, w2.w);
#pragma unroll
            for (int b = 0; b < 8; b++) { fma2(acc[2][b], wl, xl[b]); fma2(acc[2][b], wh, xh[b]); }
            wl = pk2(w3.x, w3.y); wh = pk2(w3.z, w3.w);
#pragma unroll
            for (int b = 0; b < 8; b++) { fma2(acc[3][b], wl, xl[b]); fma2(acc[3][b], wh, xh[b]); }
        }
    }
#pragma unroll
    for (int r = 0; r < 4; r++) {
#pragma unroll
        for (int b = 0; b < 8; b++) {
            float lo, hi;
            upk2(acc[r][b], lo, hi);
            float v = lo + hi;
#pragma unroll
            for (int o = 16; o; o >>= 1) v += __shfl_down_sync(0xffffffffu, v, o);
            if (lane == 0) atomicAdd(Y + (size_t)b * N + n0 + r, v);
        }
    }
}

__global__ __launch_bounds__(256, 2) void k_wo(const float* __restrict__ W) {
    gemv_nk(g_attnout, W, g_h, DIMV, DIMV, blockIdx.x, blockIdx.y * 2048, 2048);
}

// fused: moe13 (1024 blocks) + dense ffn13 (512 blocks)
__global__ __launch_bounds__(256, 2) void k_fused13(const float* __restrict__ w1,
                                                    const float* __restrict__ w3,
                                                    const float* __restrict__ m1,
                                                    const float* __restrict__ m3) {
    int id = blockIdx.x;
    if (id < 1024) {
        int e = id >> 7;
        if (!g_used[e]) return;
        int r = id & 127;
        int w13 = r & 1;
        int ksp = (r >> 1) & 1;
        int tile = r >> 2;
        const float* W = (w13 ? m3 : m1) + (size_t)e * FEV * DIMV;
        float* Y = (w13 ? g_eh3 : g_eh1) + e * BV * FEV;
        gemv_nk(g_fin, W, Y, FEV, DIMV, tile, ksp * 4096, 4096);
    } else {
        int r = id - 1024;
        int w13 = r & 1;
        int ksp = (r >> 1) & 3;
        int tile = r >> 3;
        gemv_nk(g_fin, (w13 ? w3 : w1), (w13 ? g_ffh3 : g_ffh1), FDV, DIMV,
                tile, ksp * 2048, 2048);
    }
}

// fused: moe2 (2048 blocks) + dense ffn2 (512 blocks)
__global__ __launch_bounds__(256, 2) void k_fused2(const float* __restrict__ w2,
                                                   const float* __restrict__ m2,
                                                   float* __restrict__ out) {
    int id = blockIdx.x;
    if (id < 2048) {
        int e = id >> 8;
        if (!g_used[e]) return;
        int tile = id & 255;
        gemv_nk(g_eact + e * BV * FEV, m2 + (size_t)e * DIMV * FEV, out,
                DIMV, FEV, tile, 0, FEV);
    } else {
        int r = id - 2048;
        int ksp = r & 1;
        int tile = r >> 1;
        gemv_nk(g_ffact, w2, out, DIMV, FDV, tile, ksp * 1024, 1024);
    }
}

// ---------------- gating ----------------
__global__ __launch_bounds__(256) void k_gate(const float* __restrict__ gw) {
    int b = blockIdx.x;
    int warp = threadIdx.x >> 5, lane = threadIdx.x & 31;
    __shared__ float lg[EV];
    const float* x = g_fin + b * DIMV;
    const float* w = gw + warp * DIMV;
    float s = 0.f;
    for (int k = lane * 4; k < DIMV; k += 128) {
        float4 xv = *(const float4*)(x + k);
        float4 wv = *(const float4*)(w + k);
        s += xv.x * wv.x + xv.y * wv.y + xv.z * wv.z + xv.w * wv.w;
    }
#pragma unroll
    for (int o = 16; o; o >>= 1) s += __shfl_xor_sync(0xffffffffu, s, o);
    if (lane == 0) lg[warp] = s;
    __syncthreads();
    if (threadIdx.x == 0) {
        float mx = -1e30f;
        for (int e = 0; e < EV; e++) mx = fmaxf(mx, lg[e]);
        float p[EV], sum = 0.f;
        for (int e = 0; e < EV; e++) { p[e] = __expf(lg[e] - mx); sum += p[e]; }
        for (int e = 0; e < EV; e++) p[e] /= sum;
        int i1 = 0;
        for (int e = 1; e < EV; e++) if (p[e] > p[i1]) i1 = e;
        int i2 = -1;
        for (int e = 0; e < EV; e++) if (e != i1 && (i2 < 0 || p[e] > p[i2])) i2 = e;
        for (int e = 0; e < EV; e++) g_expw[b * EV + e] = 0.f;
        g_expw[b * EV + i1] = p[i1];
        g_expw[b * EV + i2] = p[i2];
        atomicOr(&g_used[i1], 1);
        atomicOr(&g_used[i2], 1);
    }
}

// ---------------- fused activations ----------------
__global__ void k_act() {
    int i = blockIdx.x * 256 + threadIdx.x;
    if (i < BV * FDV) {
        g_ffact[i] = gelu_exact(g_ffh1[i]) * g_ffh3[i];
    } else {
        int j = i - BV * FDV;
        if (j < EV * BV * FEV) {
            int e = j >> 13;
            int b = (j >> 10) & 7;
            g_eact[j] = gelu_exact(g_eh1[j]) * g_eh3[j] * g_expw[b * EV + e];
        }
    }
}

// ---------------- launch ----------------
extern "C" void kernel_launch(void* const* d_in, const int* in_sizes, int n_in,
                              void* d_out, int out_size) {
    const float* x    = (const float*)d_in[0];
    const float* mask = (const float*)d_in[1];
    const float* fc   = (const float*)d_in[2];
    const float* fs   = (const float*)d_in[3];
    const float* ck   = (const float*)d_in[4];
    const float* cv   = (const float*)d_in[5];
    const float* wqkv = (const float*)d_in[6];
    const float* wo   = (const float*)d_in[7];
    const float* anw  = (const float*)d_in[8];
    const float* fnw  = (const float*)d_in[9];
    const float* w1   = (const float*)d_in[10];
    const float* w2   = (const float*)d_in[11];
    const float* w3   = (const float*)d_in[12];
    const float* gw   = (const float*)d_in[13];
    const float* m1   = (const float*)d_in[14];
    const float* m2   = (const float*)d_in[15];
    const float* m3   = (const float*)d_in[16];
    const int*   sp   = (const int*)d_in[17];
    float* out = (float*)d_out;

    k_init<<<148, 256>>>(x);
    k_rms1<<<8, 512>>>(x, anw);
    k_qkv<<<dim3(10, 32), 256>>>(wqkv);
    k_rope<<<160, 256>>>(fc, fs);
    k_attn<<<dim3(NSPLIT, NKV, BV), 256>>>(ck, cv, mask, sp);
    k_comb<<<64, 256>>>();
    k_wo<<<dim3(256, 4), 256>>>(wo);
    k_rms2<<<8, 512>>>(fnw, out);
    k_gate<<<8, 256>>>(gw);
    k_fused13<<<1536, 256>>>(w1, w3, m1, m3);
    k_act<<<(BV * FDV + EV * BV * FEV + 255) / 256, 256>>>();
    k_fused2<<<2560, 256>>>(w2, m2, out);
}